// round 5
// baseline (speedup 1.0000x reference)
#include <cuda_runtime.h>

#define BATCH   64
#define NTOK    4096
#define CH      1024
#define KANCH   8
#define NSPLIT  16
#define TOK_PER (NTOK / NSPLIT)   // 256
#define C4      (CH / 4)          // 256 float4 per row

// Scratch (device globals — no allocation allowed)
__device__ float    g_partial[NSPLIT * BATCH * CH];  // 4 MB
__device__ float    g_desc[BATCH * CH];              // normalized descriptors
__device__ int      g_ids[BATCH];
__device__ unsigned g_cnt[BATCH];                    // monotone arrival counters
                                                     // (old % 16 == 15 detects the
                                                     //  16th arrival of THIS replay,
                                                     //  so no reset needed)

// ---------------------------------------------------------------------------
// Fused kernel: streaming partial sums (HBM-bound, 1 GiB) + per-batch
// combiner. The 16th block to finish a batch combines its partials, computes
// the normalized descriptor, cosine sims and argmax — overlapped with the
// rest of the streaming work.
//
// Sync protocol (R3 bug fixed):
//   store partial -> __threadfence() (per-thread: orders own store)
//   -> __syncthreads() (ALL threads' fences complete)
//   -> t0 atomicAdd -> broadcast
//   reader: __threadfence() (acquire side) BEFORE reading peers' partials.
// ---------------------------------------------------------------------------
__global__ __launch_bounds__(256, 8) void k_main(const float* __restrict__ x,
                                                 const float* __restrict__ anchors,
                                                 float* __restrict__ out) {
    const int ns = blockIdx.x;
    const int b  = blockIdx.y;
    const int t  = threadIdx.x;  // 0..255 -> channels 4t..4t+3

    // ---- streaming phase (identical to proven k_partial) ----
    {
        const float4* p = reinterpret_cast<const float4*>(x)
                        + (size_t)b * NTOK * C4
                        + (size_t)ns * TOK_PER * C4
                        + t;
        float4 acc = make_float4(0.f, 0.f, 0.f, 0.f);
#pragma unroll 8
        for (int n = 0; n < TOK_PER; ++n) {
            float4 v = __ldg(p);
            p += C4;
            acc.x += v.x; acc.y += v.y; acc.z += v.z; acc.w += v.w;
        }
        reinterpret_cast<float4*>(g_partial)[(size_t)(ns * BATCH + b) * C4 + t] = acc;
    }

    // Release side: every thread fences its own store, then barrier ensures
    // all 256 threads' stores are globally visible before t0's atomic.
    __threadfence();
    __syncthreads();
    __shared__ unsigned s_old;
    if (t == 0) s_old = atomicAdd(&g_cnt[b], 1u);
    __syncthreads();
    if ((s_old & 15u) != 15u) return;   // not the last arrival for this batch

    // Acquire side: order peers' partial stores before our loads.
    __threadfence();

    // ---- combiner phase (one block per batch, 63/64 overlapped) ----
    const int lane = t & 31;
    const int w    = t >> 5;

    float4 s = make_float4(0.f, 0.f, 0.f, 0.f);
#pragma unroll
    for (int nsi = 0; nsi < NSPLIT; ++nsi) {
        float4 v = __ldcg(reinterpret_cast<const float4*>(g_partial)
                          + (size_t)(nsi * BATCH + b) * C4 + t);
        s.x += v.x; s.y += v.y; s.z += v.z; s.w += v.w;
    }
    const float inv_n = 1.0f / (float)NTOK;
    s.x *= inv_n; s.y *= inv_n; s.z *= inv_n; s.w *= inv_n;

    __shared__ float warp_s[8];
    __shared__ float s_invnorm;
    float ss = s.x * s.x + s.y * s.y + s.z * s.z + s.w * s.w;
#pragma unroll
    for (int off = 16; off > 0; off >>= 1)
        ss += __shfl_xor_sync(0xffffffffu, ss, off);
    if (lane == 0) warp_s[w] = ss;
    __syncthreads();
    if (t == 0) {
        float tot = 0.f;
#pragma unroll
        for (int i = 0; i < 8; ++i) tot += warp_s[i];
        s_invnorm = 1.0f / fmaxf(sqrtf(tot), 1e-12f);
    }
    __syncthreads();

    const float invn = s_invnorm;
    float4 d = make_float4(s.x * invn, s.y * invn, s.z * invn, s.w * invn);
    reinterpret_cast<float4*>(g_desc)[(size_t)b * C4 + t] = d;

    float dot[KANCH];
#pragma unroll
    for (int k = 0; k < KANCH; ++k) {
        float4 a = __ldg(reinterpret_cast<const float4*>(anchors) + (size_t)k * C4 + t);
        dot[k] = d.x * a.x + d.y * a.y + d.z * a.z + d.w * a.w;
    }
#pragma unroll
    for (int off = 16; off > 0; off >>= 1) {
#pragma unroll
        for (int k = 0; k < KANCH; ++k)
            dot[k] += __shfl_xor_sync(0xffffffffu, dot[k], off);
    }
    __shared__ float wd[8][KANCH];
    if (lane == 0) {
#pragma unroll
        for (int k = 0; k < KANCH; ++k) wd[w][k] = dot[k];
    }
    __syncthreads();
    if (t == 0) {
        float simk[KANCH];
#pragma unroll
        for (int k = 0; k < KANCH; ++k) {
            float acc = 0.f;
#pragma unroll
            for (int i = 0; i < 8; ++i) acc += wd[i][k];
            simk[k] = acc;
        }
        // argmin(1 - sim) == first max of sim (strict > keeps first occurrence)
        int   best   = 0;
        float best_s = simk[0];
#pragma unroll
        for (int k = 1; k < KANCH; ++k)
            if (simk[k] > best_s) { best_s = simk[k]; best = k; }
        g_ids[b] = best;
        out[b]   = (float)best;
    }
}

// ---------------------------------------------------------------------------
// EMA kernel: warp-per-anchor. The 64-step scan factors into 8 independent
// per-anchor chains (each step touches only a[k], c[k]); batch order within a
// chain is preserved => equivalent to the sequential scan. One warp owns one
// anchor's 1024 channels in registers (32/thread); per-step norm is 5
// shfl.xor ops — no barriers, no shared round-trips.
// ---------------------------------------------------------------------------
__global__ __launch_bounds__(256) void k_ema(const float* __restrict__ anchors,
                                             const float* __restrict__ counts,
                                             float* __restrict__ out) {
    const int t    = threadIdx.x;
    const int g    = t >> 5;      // warp = anchor id, 0..7
    const int lane = t & 31;

    __shared__ int s_ids[BATCH];
    if (t < BATCH) s_ids[t] = g_ids[t];
    __syncthreads();

    // Anchor state: 32 channels/thread as 8 float4s.
    // Thread lane owns C4-indices {j*32 + lane : j in 0..7} of anchor g.
    float4 A[8];
#pragma unroll
    for (int j = 0; j < 8; ++j)
        A[j] = __ldg(reinterpret_cast<const float4*>(anchors)
                     + (size_t)g * C4 + j * 32 + lane);
    float c = __ldg(counts + g);

    for (int b = 0; b < BATCH; ++b) {
        if (s_ids[b] != g) continue;

        const float m  = (c < 1.0f) ? 0.0f : 0.9f;
        const float im = 1.0f - m;

        float4 V[8];
        float  ss = 0.f;
#pragma unroll
        for (int j = 0; j < 8; ++j) {
            float4 d = reinterpret_cast<const float4*>(g_desc)[(size_t)b * C4 + j * 32 + lane];
            V[j].x = m * A[j].x + im * d.x;
            V[j].y = m * A[j].y + im * d.y;
            V[j].z = m * A[j].z + im * d.z;
            V[j].w = m * A[j].w + im * d.w;
            ss += V[j].x * V[j].x + V[j].y * V[j].y
                + V[j].z * V[j].z + V[j].w * V[j].w;
        }
#pragma unroll
        for (int off = 16; off > 0; off >>= 1)
            ss += __shfl_xor_sync(0xffffffffu, ss, off);
        const float inv = 1.0f / fmaxf(sqrtf(ss), 1e-12f);
#pragma unroll
        for (int j = 0; j < 8; ++j) {
            A[j].x = V[j].x * inv; A[j].y = V[j].y * inv;
            A[j].z = V[j].z * inv; A[j].w = V[j].w * inv;
        }
        c += 1.0f;
    }

    // Emit new_anchors then new_counts (after the 64 ids)
#pragma unroll
    for (int j = 0; j < 8; ++j)
        reinterpret_cast<float4*>(out + BATCH)[(size_t)g * C4 + j * 32 + lane] = A[j];
    if (lane == 0) out[BATCH + KANCH * CH + g] = c;
}

// ---------------------------------------------------------------------------
extern "C" void kernel_launch(void* const* d_in, const int* in_sizes, int n_in,
                              void* d_out, int out_size) {
    const float* prompt_tokens = (const float*)d_in[0];  // [64,4096,1024] f32
    const float* anchors       = (const float*)d_in[1];  // [8,1024] f32
    const float* counts        = (const float*)d_in[2];  // [8] f32
    float* out = (float*)d_out;  // [64 ids | 8192 anchors | 8 counts] f32

    dim3 grid1(NSPLIT, BATCH);
    k_main<<<grid1, 256>>>(prompt_tokens, anchors, out);
    k_ema<<<1, 256>>>(anchors, counts, out);
}

// round 6
// speedup vs baseline: 1.0157x; 1.0157x over previous
#include <cuda_runtime.h>

#define BATCH   64
#define NTOK    4096
#define CH      1024
#define KANCH   8
#define NSPLIT  16
#define TOK_PER (NTOK / NSPLIT)   // 256
#define C4      (CH / 4)          // 256 float4 per row

// Scratch (device globals — no allocation allowed)
__device__ float    g_partial[NSPLIT * BATCH * CH];  // 4 MB
__device__ float    g_desc[BATCH * CH];              // normalized descriptors
__device__ int      g_ids[BATCH];
__device__ unsigned g_cnt[BATCH];                    // monotone arrival counters
                                                     // (old % 16 == 15 detects the
                                                     //  16th arrival of THIS replay,
                                                     //  so no reset needed)

// ---------------------------------------------------------------------------
// Fused kernel: streaming partial sums (HBM-bound, 1 GiB) + per-batch
// combiner. The 16th block to finish a batch combines its partials, computes
// the normalized descriptor, cosine sims and argmax — overlapped with the
// rest of the streaming work. Measured ~149-151us (DRAM ~87% = ceiling).
//
// Sync protocol:
//   store partial -> __threadfence() (per-thread: orders own store)
//   -> __syncthreads() (ALL threads' fences complete)
//   -> t0 atomicAdd -> broadcast
//   reader: __threadfence() (acquire side) BEFORE reading peers' partials.
// ---------------------------------------------------------------------------
__global__ __launch_bounds__(256, 8) void k_main(const float* __restrict__ x,
                                                 const float* __restrict__ anchors,
                                                 float* __restrict__ out) {
    const int ns = blockIdx.x;
    const int b  = blockIdx.y;
    const int t  = threadIdx.x;  // 0..255 -> channels 4t..4t+3

    // ---- streaming phase ----
    {
        const float4* p = reinterpret_cast<const float4*>(x)
                        + (size_t)b * NTOK * C4
                        + (size_t)ns * TOK_PER * C4
                        + t;
        float4 acc = make_float4(0.f, 0.f, 0.f, 0.f);
#pragma unroll 8
        for (int n = 0; n < TOK_PER; ++n) {
            float4 v = __ldg(p);
            p += C4;
            acc.x += v.x; acc.y += v.y; acc.z += v.z; acc.w += v.w;
        }
        reinterpret_cast<float4*>(g_partial)[(size_t)(ns * BATCH + b) * C4 + t] = acc;
    }

    __threadfence();
    __syncthreads();
    __shared__ unsigned s_old;
    if (t == 0) s_old = atomicAdd(&g_cnt[b], 1u);
    __syncthreads();
    if ((s_old & 15u) != 15u) return;   // not the last arrival for this batch

    __threadfence();   // acquire: order peers' partial stores before our loads

    // ---- combiner phase (one block per batch, 63/64 overlapped) ----
    const int lane = t & 31;
    const int w    = t >> 5;

    float4 s = make_float4(0.f, 0.f, 0.f, 0.f);
#pragma unroll
    for (int nsi = 0; nsi < NSPLIT; ++nsi) {
        float4 v = __ldcg(reinterpret_cast<const float4*>(g_partial)
                          + (size_t)(nsi * BATCH + b) * C4 + t);
        s.x += v.x; s.y += v.y; s.z += v.z; s.w += v.w;
    }
    const float inv_n = 1.0f / (float)NTOK;
    s.x *= inv_n; s.y *= inv_n; s.z *= inv_n; s.w *= inv_n;

    __shared__ float warp_s[8];
    __shared__ float s_invnorm;
    float ss = s.x * s.x + s.y * s.y + s.z * s.z + s.w * s.w;
#pragma unroll
    for (int off = 16; off > 0; off >>= 1)
        ss += __shfl_xor_sync(0xffffffffu, ss, off);
    if (lane == 0) warp_s[w] = ss;
    __syncthreads();
    if (t == 0) {
        float tot = 0.f;
#pragma unroll
        for (int i = 0; i < 8; ++i) tot += warp_s[i];
        s_invnorm = 1.0f / fmaxf(sqrtf(tot), 1e-12f);
    }
    __syncthreads();

    const float invn = s_invnorm;
    float4 d = make_float4(s.x * invn, s.y * invn, s.z * invn, s.w * invn);
    reinterpret_cast<float4*>(g_desc)[(size_t)b * C4 + t] = d;

    float dot[KANCH];
#pragma unroll
    for (int k = 0; k < KANCH; ++k) {
        float4 a = __ldg(reinterpret_cast<const float4*>(anchors) + (size_t)k * C4 + t);
        dot[k] = d.x * a.x + d.y * a.y + d.z * a.z + d.w * a.w;
    }
#pragma unroll
    for (int off = 16; off > 0; off >>= 1) {
#pragma unroll
        for (int k = 0; k < KANCH; ++k)
            dot[k] += __shfl_xor_sync(0xffffffffu, dot[k], off);
    }
    __shared__ float wd[8][KANCH];
    if (lane == 0) {
#pragma unroll
        for (int k = 0; k < KANCH; ++k) wd[w][k] = dot[k];
    }
    __syncthreads();
    if (t == 0) {
        float simk[KANCH];
#pragma unroll
        for (int k = 0; k < KANCH; ++k) {
            float acc = 0.f;
#pragma unroll
            for (int i = 0; i < 8; ++i) acc += wd[i][k];
            simk[k] = acc;
        }
        // argmin(1 - sim) == first max of sim (strict > keeps first occurrence)
        int   best   = 0;
        float best_s = simk[0];
#pragma unroll
        for (int k = 1; k < KANCH; ++k)
            if (simk[k] > best_s) { best_s = simk[k]; best = k; }
        g_ids[b] = best;
        out[b]   = (float)best;
    }
}

// ---------------------------------------------------------------------------
// EMA kernel: warp-per-anchor (8 independent chains; in-chain batch order
// preserved => equivalent to the sequential scan). State is A[8] float4 = 32
// regs, updated IN PLACE (no V copy -> no spills; R5's 21us was local-memory
// spill traffic from 64 live floats). Sample lists prebuilt in shared. Norm:
// 4-way accumulators + 5 shfl.xor + rsqrtf (ss in [~0.64,1.21], far from eps).
// ---------------------------------------------------------------------------
__global__ __launch_bounds__(256) void k_ema(const float* __restrict__ anchors,
                                             const float* __restrict__ counts,
                                             float* __restrict__ out) {
    const int t    = threadIdx.x;
    const int g    = t >> 5;      // warp = anchor id, 0..7
    const int lane = t & 31;

    __shared__ int s_list[KANCH][BATCH];
    __shared__ int s_len[KANCH];
    if (t < KANCH) {
        int n = 0;
        for (int b = 0; b < BATCH; ++b)
            if (g_ids[b] == t) s_list[t][n++] = b;
        s_len[t] = n;
    }
    __syncthreads();
    const int len = s_len[g];

    // Thread lane owns C4-indices {j*32 + lane : j in 0..7} of anchor g.
    float4 A[8];
#pragma unroll
    for (int j = 0; j < 8; ++j)
        A[j] = __ldg(reinterpret_cast<const float4*>(anchors)
                     + (size_t)g * C4 + j * 32 + lane);
    float c = __ldg(counts + g);

    for (int i = 0; i < len; ++i) {
        const int b = s_list[g][i];           // warp-uniform broadcast
        const float m  = (c < 1.0f) ? 0.0f : 0.9f;
        const float im = 1.0f - m;

        float s0 = 0.f, s1 = 0.f, s2 = 0.f, s3 = 0.f;
#pragma unroll
        for (int j = 0; j < 8; ++j) {
            float4 d = reinterpret_cast<const float4*>(g_desc)[(size_t)b * C4 + j * 32 + lane];
            A[j].x = m * A[j].x + im * d.x;
            A[j].y = m * A[j].y + im * d.y;
            A[j].z = m * A[j].z + im * d.z;
            A[j].w = m * A[j].w + im * d.w;
            s0 += A[j].x * A[j].x;
            s1 += A[j].y * A[j].y;
            s2 += A[j].z * A[j].z;
            s3 += A[j].w * A[j].w;
        }
        float ss = (s0 + s1) + (s2 + s3);
#pragma unroll
        for (int off = 16; off > 0; off >>= 1)
            ss += __shfl_xor_sync(0xffffffffu, ss, off);
        const float inv = rsqrtf(ss);
#pragma unroll
        for (int j = 0; j < 8; ++j) {
            A[j].x *= inv; A[j].y *= inv;
            A[j].z *= inv; A[j].w *= inv;
        }
        c += 1.0f;
    }

    // Emit new_anchors then new_counts (after the 64 ids)
#pragma unroll
    for (int j = 0; j < 8; ++j)
        reinterpret_cast<float4*>(out + BATCH)[(size_t)g * C4 + j * 32 + lane] = A[j];
    if (lane == 0) out[BATCH + KANCH * CH + g] = c;
}

// ---------------------------------------------------------------------------
extern "C" void kernel_launch(void* const* d_in, const int* in_sizes, int n_in,
                              void* d_out, int out_size) {
    const float* prompt_tokens = (const float*)d_in[0];  // [64,4096,1024] f32
    const float* anchors       = (const float*)d_in[1];  // [8,1024] f32
    const float* counts        = (const float*)d_in[2];  // [8] f32
    float* out = (float*)d_out;  // [64 ids | 8192 anchors | 8 counts] f32

    dim3 grid1(NSPLIT, BATCH);
    k_main<<<grid1, 256>>>(prompt_tokens, anchors, out);
    k_ema<<<1, 256>>>(anchors, counts, out);
}